// round 6
// baseline (speedup 1.0000x reference)
#include <cuda_runtime.h>
#include <cuda_fp16.h>

// DigitCaps dynamic routing — fused, line-optimal W loads.
// u[B=256, N=1152, IC=8], W[K=10, N=1152, IC=8, OC=16] -> v [K, B, 1, 1, 16]
//
// Block = (k, 4 batches), 576 threads, grid (64, 10).
// Phase1 lane map: og=lane&3 (4 o's), ip=(lane>>2)&1 (even/odd i), ns4=lane>>3
// (4 rows). Each W LDG.128 covers 4 full 128B lines (optimal wavefronts).
// Partial i-sums combined with one shfl_xor(4); uh stored fp16 packed
// [n][og][bp][oo][bbin] (one STS.128 per lane per row-slot).
// u staged parity-deinterleaved in smem (pad stride 148, conflict-free).
// Routing logits in registers; phases as in round 5 adapted to new uh layout.

#define KC   10
#define BB   256
#define NN   1152
#define IC   8
#define OC   16
#define TPB  576
#define NW   18
#define BPB  4
#define CN   144
#define NCHK 8
#define NSEG 72
#define USTR 148
#define FULL 0xffffffffu

__global__ __launch_bounds__(TPB, 1)
void digitcaps_fused(const float* __restrict__ u,
                     const float* __restrict__ W,
                     float* __restrict__ out)
{
    extern __shared__ char sm[];
    half*  uh   = (half*)sm;                        // [NN][4 og][2 bp][8] halves, 147456 B
    float* eb   = (float*)(sm + NN * 64 * 2);       // [4][NN]
    float* usp  = eb + 4 * NN;                      // us[4][2][148][4] | sp[4][72][16]
    float* sp   = usp;
    float* sp2  = usp + 4736;                       // [4][4][16]
    float* redS = sp2 + 256;                        // [18][4 og][4 bb][4 oo]
    float* rede = redS + 1152;                      // [18][4]
    float* vB   = rede + 72;                        // [4][16]

    const int k    = blockIdx.y;
    const int b0   = blockIdx.x * BPB;
    const int t    = threadIdx.x;
    const int w    = t >> 5;
    const int lane = t & 31;
    const int og   = lane & 3;
    const int ip   = (lane >> 2) & 1;
    const int ns4  = lane >> 3;

    const float* Wk = W + (size_t)k * NN * 128;

    float4 s0a[BPB];
    #pragma unroll
    for (int bb = 0; bb < BPB; ++bb) s0a[bb] = make_float4(0.f, 0.f, 0.f, 0.f);

    // ---------------- phase 1: u_hat ----------------
    for (int c = 0; c < NCHK; ++c) {
        __syncthreads();
        // stage u parity-deinterleaved
        #pragma unroll
        for (int q = 0; q < 2; ++q) {
            int idx = t + q * TPB;                      // 0..1151
            int bb = idx / 288;
            int r  = idx - bb * 288;
            int nl = r >> 1, h = r & 1;
            float4 x = *(const float4*)(u + ((size_t)(b0 + bb) * NN + c * CN + nl) * IC + h * 4);
            *(float2*)(usp + ((bb * 2 + 0) * USTR + nl) * 4 + h * 2) = make_float2(x.x, x.z);
            *(float2*)(usp + ((bb * 2 + 1) * USTR + nl) * 4 + h * 2) = make_float2(x.y, x.w);
        }
        __syncthreads();

        #pragma unroll
        for (int g = 0; g < 2; ++g) {
            const int nl = (w * 2 + g) * 4 + ns4;
            const int n  = c * CN + nl;
            float4 wv[4];
            #pragma unroll
            for (int i0 = 0; i0 < 4; ++i0)
                wv[i0] = *(const float4*)(Wk + (size_t)n * 128 + (2 * i0 + ip) * 16 + og * 4);
            float4 u4[BPB];
            #pragma unroll
            for (int bb = 0; bb < BPB; ++bb)
                u4[bb] = *(const float4*)(usp + ((bb * 2 + ip) * USTR + nl) * 4);

            float4 acc[BPB];
            #pragma unroll
            for (int bb = 0; bb < BPB; ++bb) acc[bb] = make_float4(0.f, 0.f, 0.f, 0.f);
            #pragma unroll
            for (int i0 = 0; i0 < 4; ++i0) {
                #pragma unroll
                for (int bb = 0; bb < BPB; ++bb) {
                    float f = ((const float*)&u4[bb])[i0];
                    acc[bb].x = fmaf(f, wv[i0].x, acc[bb].x);
                    acc[bb].y = fmaf(f, wv[i0].y, acc[bb].y);
                    acc[bb].z = fmaf(f, wv[i0].z, acc[bb].z);
                    acc[bb].w = fmaf(f, wv[i0].w, acc[bb].w);
                }
            }
            // s0 from partials (both ip halves sum correctly in final reduce)
            #pragma unroll
            for (int bb = 0; bb < BPB; ++bb) {
                s0a[bb].x += acc[bb].x; s0a[bb].y += acc[bb].y;
                s0a[bb].z += acc[bb].z; s0a[bb].w += acc[bb].w;
            }
            // combine even/odd i halves
            #pragma unroll
            for (int bb = 0; bb < BPB; ++bb) {
                acc[bb].x += __shfl_xor_sync(FULL, acc[bb].x, 4);
                acc[bb].y += __shfl_xor_sync(FULL, acc[bb].y, 4);
                acc[bb].z += __shfl_xor_sync(FULL, acc[bb].z, 4);
                acc[bb].w += __shfl_xor_sync(FULL, acc[bb].w, 4);
            }
            // store bb-pair for this ip lane: [n][og][bp=ip][oo][bbin]
            float4 e0 = acc[2 * ip], e1 = acc[2 * ip + 1];
            uint4 pk;
            pk.x = __half2_raw(__floats2half2_rn(e0.x, e1.x)).x | ((unsigned)__half2_raw(__floats2half2_rn(e0.x, e1.x)).y << 16);
            // (use direct half2 stores instead for clarity)
            half2* dst = (half2*)(uh + ((size_t)(n * 4 + og) * 2 + ip) * 8);
            dst[0] = __floats2half2_rn(e0.x, e1.x);
            dst[1] = __floats2half2_rn(e0.y, e1.y);
            dst[2] = __floats2half2_rn(e0.z, e1.z);
            dst[3] = __floats2half2_rn(e0.w, e1.w);
            (void)pk;
        }
    }
    // reduce s0 over ip (4), ns4 (8,16) lanes — og preserved
    #pragma unroll
    for (int d = 4; d <= 16; d <<= 1) {
        #pragma unroll
        for (int bb = 0; bb < BPB; ++bb) {
            s0a[bb].x += __shfl_xor_sync(FULL, s0a[bb].x, d);
            s0a[bb].y += __shfl_xor_sync(FULL, s0a[bb].y, d);
            s0a[bb].z += __shfl_xor_sync(FULL, s0a[bb].z, d);
            s0a[bb].w += __shfl_xor_sync(FULL, s0a[bb].w, d);
        }
    }
    if (lane < 4) {
        #pragma unroll
        for (int bb = 0; bb < BPB; ++bb)
            *(float4*)(redS + ((w * 4 + lane) * 4 + bb) * 4) = s0a[bb];
    }
    __syncthreads();

    // ---------------- routing iterations ----------------
    float br[BPB][2];

    #pragma unroll 1
    for (int it = 0; it < 3; ++it) {
        // v-compute: 64 threads, one per (bb, o)
        if (t < 64) {
            const int bb = t >> 4, o = t & 15;
            float s = 0.0f, S;
            if (it == 0) {
                #pragma unroll
                for (int q = 0; q < NW; ++q)
                    s += redS[((q * 4 + (o >> 2)) * 4 + bb) * 4 + (o & 3)];
                S = (float)NN;
            } else {
                #pragma unroll
                for (int q = 0; q < 4; ++q) s += sp2[(bb * 4 + q) * 16 + o];
                S = 0.0f;
                #pragma unroll
                for (int q = 0; q < NW; ++q) S += rede[q * 4 + bb];
            }
            float x = s / S;
            float sq = x * x;
            sq += __shfl_xor_sync(FULL, sq, 1);
            sq += __shfl_xor_sync(FULL, sq, 2);
            sq += __shfl_xor_sync(FULL, sq, 4);
            sq += __shfl_xor_sync(FULL, sq, 8);
            float vv = x * (sq / ((1.0f + sq) * sqrtf(sq)));
            if (it == 2)
                out[((size_t)k * BB + (b0 + bb)) * OC + o] = vv;
            else
                vB[bb * OC + o] = vv;
        }
        if (it == 2) return;
        __syncthreads();

        // phase2a: a=<uh,v>, b+=a, e=exp(b), per bb-pair
        #pragma unroll
        for (int bp = 0; bp < 2; ++bp) {
            const int be = 2 * bp, bo = 2 * bp + 1;
            float4 ve0 = *(const float4*)(vB + be * OC + 0);
            float4 ve1 = *(const float4*)(vB + be * OC + 4);
            float4 ve2 = *(const float4*)(vB + be * OC + 8);
            float4 ve3 = *(const float4*)(vB + be * OC + 12);
            float4 vo0 = *(const float4*)(vB + bo * OC + 0);
            float4 vo1 = *(const float4*)(vB + bo * OC + 4);
            float4 vo2 = *(const float4*)(vB + bo * OC + 8);
            float4 vo3 = *(const float4*)(vB + bo * OC + 12);
            float ese = 0.0f, eso = 0.0f;
            #pragma unroll
            for (int r = 0; r < 2; ++r) {
                const int n = t + r * TPB;
                float ae = 0.0f, ao = 0.0f;
                #pragma unroll
                for (int g2 = 0; g2 < 4; ++g2) {
                    const half2* q = (const half2*)(uh + ((size_t)(n * 4 + g2) * 2 + bp) * 8);
                    const float4 vve = (g2 == 0) ? ve0 : (g2 == 1) ? ve1 : (g2 == 2) ? ve2 : ve3;
                    const float4 vvo = (g2 == 0) ? vo0 : (g2 == 1) ? vo1 : (g2 == 2) ? vo2 : vo3;
                    float2 p;
                    p = __half22float2(q[0]); ae = fmaf(p.x, vve.x, ae); ao = fmaf(p.y, vvo.x, ao);
                    p = __half22float2(q[1]); ae = fmaf(p.x, vve.y, ae); ao = fmaf(p.y, vvo.y, ao);
                    p = __half22float2(q[2]); ae = fmaf(p.x, vve.z, ae); ao = fmaf(p.y, vvo.z, ao);
                    p = __half22float2(q[3]); ae = fmaf(p.x, vve.w, ae); ao = fmaf(p.y, vvo.w, ao);
                }
                float bne = (it == 0) ? ae : (br[be][r] + ae);
                float bno = (it == 0) ? ao : (br[bo][r] + ao);
                br[be][r] = bne; br[bo][r] = bno;
                float e0 = __expf(bne), e1 = __expf(bno);
                ese += e0; eso += e1;
                eb[be * NN + n] = e0;
                eb[bo * NN + n] = e1;
            }
            #pragma unroll
            for (int d = 16; d >= 1; d >>= 1) {
                ese += __shfl_xor_sync(FULL, ese, d);
                eso += __shfl_xor_sync(FULL, eso, d);
            }
            if (lane == 0) { rede[w * 4 + be] = ese; rede[w * 4 + bo] = eso; }
        }
        __syncthreads();

        // phase2b: s accumulation. slot: sg = t>>3, og2 = (t>>1)&3, bp2 = t&1
        {
            const int sg = t >> 3, og2 = (t >> 1) & 3, bp2 = t & 1;
            const int be = 2 * bp2, bo = 2 * bp2 + 1;
            float se0 = 0, se1 = 0, se2 = 0, se3 = 0;
            float so0 = 0, so1 = 0, so2 = 0, so3 = 0;
            #pragma unroll
            for (int i = 0; i < 16; ++i) {
                const int n = sg * 16 + i;
                const half2* q = (const half2*)(uh + ((size_t)(n * 4 + og2) * 2 + bp2) * 8);
                float e0 = eb[be * NN + n], e1 = eb[bo * NN + n];
                float2 p;
                p = __half22float2(q[0]); se0 = fmaf(e0, p.x, se0); so0 = fmaf(e1, p.y, so0);
                p = __half22float2(q[1]); se1 = fmaf(e0, p.x, se1); so1 = fmaf(e1, p.y, so1);
                p = __half22float2(q[2]); se2 = fmaf(e0, p.x, se2); so2 = fmaf(e1, p.y, so2);
                p = __half22float2(q[3]); se3 = fmaf(e0, p.x, se3); so3 = fmaf(e1, p.y, so3);
            }
            *(float4*)(sp + ((size_t)be * NSEG + sg) * 16 + og2 * 4) = make_float4(se0, se1, se2, se3);
            *(float4*)(sp + ((size_t)bo * NSEG + sg) * 16 + og2 * 4) = make_float4(so0, so1, so2, so3);
        }
        __syncthreads();

        // stage A: 72 -> 4 partials per (bb, o)
        if (t < 256) {
            const int bb = t >> 6, q = (t >> 4) & 3, o = t & 15;
            float s = 0.0f;
            #pragma unroll
            for (int r = 0; r < 18; ++r)
                s += sp[((size_t)bb * NSEG + q * 18 + r) * 16 + o];
            sp2[(bb * 4 + q) * 16 + o] = s;
        }
        __syncthreads();
    }
}

extern "C" void kernel_launch(void* const* d_in, const int* in_sizes, int n_in,
                              void* d_out, int out_size)
{
    const float* u = (const float*)d_in[0];
    const float* W = (const float*)d_in[1];
    if (n_in >= 2 && in_sizes[0] == KC * NN * IC * OC) {
        const float* tp = u; u = W; W = tp;
    }
    float* out = (float*)d_out;

    const int smem_bytes = NN * 64 * 2                       // uh
                         + (4 * NN + 4736 + 256 + 1152 + 72 + 64) * 4;
    cudaFuncSetAttribute(digitcaps_fused,
                         cudaFuncAttributeMaxDynamicSharedMemorySize, smem_bytes);

    dim3 grid(BB / BPB, KC);
    digitcaps_fused<<<grid, TPB, smem_bytes>>>(u, W, out);
}